// round 1
// baseline (speedup 1.0000x reference)
#include <cuda_runtime.h>
#include <math.h>

#define Nn 60000
#define Dd 512
#define HH 245
#define NPOS 60025
#define NSEQ 60026
#define SST 60032
#define NBLK7 296
#define CHUNK7 203
#define INV_SQRT_D 0.04419417382415922f

// ---------------- scratch (device globals: allocation-free) ----------------
__device__ unsigned long long g_key;
__device__ int   g_idx;
__device__ float g_q[Dd];
__device__ float g_u[8 * Dd];
__device__ float g_c[8];
__device__ float g_xx[NPOS * Dd];          // ~123 MB conv output (xseq rows 1..)
__device__ float g_scores[8 * SST];
__device__ float g_w[8 * SST];             // normalized attention weights
__device__ float g_spart[NBLK7 * 4096];
__device__ float g_s[4096];                // s[h][e] = sum_p attn[h,p]*xseq[p,e]
__device__ float g_O[Dd];
__device__ float g_O2[Dd];

// ---------------- K0: per-launch init ----------------
__global__ void k_init() { g_key = 0ull; }

// ---------------- K1: a1 = sigmoid(inputs@w_enc+b), A1 out, argmax ----------------
__global__ void k_enc(const float* __restrict__ inputs,
                      const float* __restrict__ w_enc,
                      const float* __restrict__ b_enc,
                      float* __restrict__ a1_out) {
    __shared__ float w_sh[Dd];
    __shared__ unsigned long long keys[8];
    int t = threadIdx.x;               // 256 threads, 8 warps
    w_sh[t] = w_enc[t];
    w_sh[t + 256] = w_enc[t + 256];
    __syncthreads();
    int warp = t >> 5, lane = t & 31;
    int row = blockIdx.x * 8 + warp;
    float acc = 0.f;
    const float4* rp = (const float4*)(inputs + (size_t)row * Dd);
#pragma unroll
    for (int k = 0; k < 4; k++) {
        float4 v = rp[lane + 32 * k];
        const float* ws = &w_sh[(lane + 32 * k) * 4];
        acc += v.x * ws[0] + v.y * ws[1] + v.z * ws[2] + v.w * ws[3];
    }
#pragma unroll
    for (int o = 16; o; o >>= 1) acc += __shfl_xor_sync(0xFFFFFFFFu, acc, o);
    if (lane == 0) {
        float val = acc + b_enc[0];
        a1_out[row] = 1.0f / (1.0f + expf(-val));
        unsigned u = __float_as_uint(val);
        u = (u & 0x80000000u) ? ~u : (u | 0x80000000u);
        keys[warp] = ((unsigned long long)u << 32) | (unsigned long long)(0xFFFFFFFFu - (unsigned)row);
    }
    __syncthreads();
    if (t == 0) {
        unsigned long long k = keys[0];
#pragma unroll
        for (int i = 1; i < 8; i++) k = (keys[i] > k) ? keys[i] : k;
        atomicMax(&g_key, k);
    }
}

__global__ void k_decode() {
    g_idx = (int)(0xFFFFFFFFu - (unsigned)(g_key & 0xFFFFFFFFull));
}

// ---------------- K2: q = inputs[idx] @ w_q + b_q ----------------
__global__ void k_q(const float* __restrict__ inputs,
                    const float* __restrict__ w_q,
                    const float* __restrict__ b_q) {
    __shared__ float Qs[Dd];
    int t = threadIdx.x;               // 64
    int d = blockIdx.x * 64 + t;
    const float* Q = inputs + (size_t)g_idx * Dd;
    for (int i = t; i < Dd; i += 64) Qs[i] = Q[i];
    __syncthreads();
    float acc = 0.f;
#pragma unroll 8
    for (int e = 0; e < Dd; e++) acc += Qs[e] * w_q[e * Dd + d];
    g_q[d] = acc + b_q[d];
}

// ---------------- K3: u[h][e] = sum_j w_k[e, h*64+j]*q[h*64+j]; c[h] ----------------
__global__ void k_u(const float* __restrict__ w_k,
                    const float* __restrict__ b_k) {
    __shared__ float qs[Dd];
    int t = threadIdx.x;               // 512
    qs[t] = g_q[t];
    __syncthreads();
    int g = blockIdx.x * 512 + t;      // 8 blocks -> 4096 (e,h) pairs
    int e = g >> 3, h = g & 7;
    const float* wr = w_k + (size_t)e * Dd + h * 64;
    const float* qh = &qs[h * 64];
    float acc = 0.f;
#pragma unroll 8
    for (int j = 0; j < 64; j++) acc += wr[j] * qh[j];
    g_u[h * Dd + e] = acc;
    if (g < 8) {
        float cc = 0.f;
        for (int j = 0; j < 64; j++) cc += b_k[g * 64 + j] * qs[g * 64 + j];
        g_c[g] = cc;
    }
}

// ---------------- K5: fused xs=relu(x-Q) + depthwise 3x3 conv + residual ----------------
__device__ __forceinline__ float xp_val(const float* __restrict__ inp,
                                        int rr, int cc, int d, float Qd) {
    if (rr < 0 || rr >= HH || cc < 0 || cc >= HH) return 0.f;
    int pos = rr * HH + cc;
    int src = (pos >= Nn) ? pos - Nn : pos;
    return fmaxf(inp[(size_t)src * Dd + d] - Qd, 0.f);
}

__global__ void k_conv(const float* __restrict__ inputs,
                       const float* __restrict__ conv_w,
                       const float* __restrict__ conv_b,
                       float* __restrict__ ishift) {
    int d = threadIdx.x;               // 512 (one per channel)
    int r = blockIdx.y;                // grid row
    int c0 = blockIdx.x * 32;          // 8 col-segments of 32
    if (c0 >= HH) return;
    int cend = min(HH, c0 + 32);
    float w[9];
#pragma unroll
    for (int k = 0; k < 9; k++) w[k] = conv_w[d * 9 + k];
    float cb = conv_b[d];
    int idx = g_idx;
    float Qd = inputs[(size_t)idx * Dd + d];

    float a0 = xp_val(inputs, r - 1, c0 - 1, d, Qd), a1 = xp_val(inputs, r - 1, c0, d, Qd);
    float b0 = xp_val(inputs, r,     c0 - 1, d, Qd), b1 = xp_val(inputs, r,     c0, d, Qd);
    float e0 = xp_val(inputs, r + 1, c0 - 1, d, Qd), e1 = xp_val(inputs, r + 1, c0, d, Qd);

    for (int c = c0; c < cend; c++) {
        float a2 = xp_val(inputs, r - 1, c + 1, d, Qd);
        float b2 = xp_val(inputs, r,     c + 1, d, Qd);
        float e2 = xp_val(inputs, r + 1, c + 1, d, Qd);
        float xx = b1 + cb
                 + w[0] * a0 + w[1] * a1 + w[2] * a2
                 + w[3] * b0 + w[4] * b1 + w[5] * b2
                 + w[6] * e0 + w[7] * e1 + w[8] * e2;
        int pos = r * HH + c;
        if (pos < Nn) ishift[(size_t)pos * Dd + d] = b1;
        g_xx[(size_t)pos * Dd + d] = xx;
        a0 = a1; a1 = a2; b0 = b1; b1 = b2; e0 = e1; e1 = e2;
    }
}

// ---------------- K6a: scores[h,p] = (xseq[p].u_h + c_h)/sqrt(D) ----------------
__global__ void k_scores(const float* __restrict__ cls) {
    __shared__ float4 u_sh[8 * 128];   // u as float4 per head
    int t = threadIdx.x;               // 256, 8 warps
    float* uf = (float*)u_sh;
    for (int i = t; i < 4096; i += 256) uf[i] = g_u[i];
    __syncthreads();
    int warp = t >> 5, lane = t & 31;
    int stride = gridDim.x * 8;
    for (int p = blockIdx.x * 8 + warp; p < NSEQ; p += stride) {
        const float4* rp = (p == 0) ? (const float4*)cls
                                    : (const float4*)(g_xx + (size_t)(p - 1) * Dd);
        float4 rv[4];
#pragma unroll
        for (int k = 0; k < 4; k++) rv[k] = rp[k * 32 + lane];
        float sc[8];
#pragma unroll
        for (int h = 0; h < 8; h++) {
            float acc = 0.f;
#pragma unroll
            for (int k = 0; k < 4; k++) {
                float4 u = u_sh[h * 128 + k * 32 + lane];
                acc += rv[k].x * u.x + rv[k].y * u.y + rv[k].z * u.z + rv[k].w * u.w;
            }
            sc[h] = acc;
        }
#pragma unroll
        for (int h = 0; h < 8; h++)
#pragma unroll
            for (int o = 16; o; o >>= 1) sc[h] += __shfl_xor_sync(0xFFFFFFFFu, sc[h], o);
        if (lane < 8) g_scores[lane * SST + p] = (sc[lane] + g_c[lane]) * INV_SQRT_D;
    }
}

// ---------------- K6b: softmax per head -> normalized weights ----------------
__global__ void k_softmax() {
    int h = blockIdx.x, t = threadIdx.x;   // 8 x 256
    __shared__ float red[256];
    const float* s = g_scores + h * SST;
    float m = -1e30f;
    for (int p = t; p < NSEQ; p += 256) m = fmaxf(m, s[p]);
    red[t] = m; __syncthreads();
    for (int o = 128; o; o >>= 1) { if (t < o) red[t] = fmaxf(red[t], red[t + o]); __syncthreads(); }
    m = red[0]; __syncthreads();
    float sum = 0.f;
    for (int p = t; p < NSEQ; p += 256) sum += expf(s[p] - m);
    red[t] = sum; __syncthreads();
    for (int o = 128; o; o >>= 1) { if (t < o) red[t] += red[t + o]; __syncthreads(); }
    float inv = 1.0f / red[0];
    for (int p = t; p < NSEQ; p += 256) g_w[h * SST + p] = expf(s[p] - m) * inv;
}

// ---------------- K7: s[h][e] = sum_p w[h,p]*xseq[p,e] (block partials) ----------------
__global__ void k_wsum(const float* __restrict__ cls) {
    int b = blockIdx.x, t = threadIdx.x;   // NBLK7 x 128 (float4 channels)
    int p0 = b * CHUNK7;
    int p1 = min(NSEQ, p0 + CHUNK7);
    __shared__ float wsh[CHUNK7 * 8];
    for (int i = t; i < (p1 - p0) * 8; i += 128) {
        int pp = i >> 3, h = i & 7;
        wsh[i] = g_w[h * SST + p0 + pp];
    }
    __syncthreads();
    float acc[8][4];
#pragma unroll
    for (int h = 0; h < 8; h++) { acc[h][0] = acc[h][1] = acc[h][2] = acc[h][3] = 0.f; }
    for (int p = p0; p < p1; p++) {
        const float4* rp = (p == 0) ? (const float4*)cls
                                    : (const float4*)(g_xx + (size_t)(p - 1) * Dd);
        float4 v = rp[t];
        const float* wp = &wsh[(p - p0) * 8];
#pragma unroll
        for (int h = 0; h < 8; h++) {
            float w = wp[h];
            acc[h][0] += w * v.x; acc[h][1] += w * v.y;
            acc[h][2] += w * v.z; acc[h][3] += w * v.w;
        }
    }
    float* outp = g_spart + (size_t)b * 4096;
#pragma unroll
    for (int h = 0; h < 8; h++)
        ((float4*)(outp + h * Dd))[t] = make_float4(acc[h][0], acc[h][1], acc[h][2], acc[h][3]);
}

__global__ void k_wred() {
    int i = blockIdx.x * 256 + threadIdx.x;  // 16 x 256 = 4096
    float acc = 0.f;
    for (int b = 0; b < NBLK7; b++) acc += g_spart[(size_t)b * 4096 + i];
    g_s[i] = acc;
}

// ---------------- K8: O[d] = q[d] + s[h].w_v[:,d] + b_v[d] ----------------
__global__ void k_av(const float* __restrict__ w_v, const float* __restrict__ b_v) {
    __shared__ float s_sh[Dd];
    int t = threadIdx.x;               // 64
    int h = blockIdx.x;                // 8
    int d = h * 64 + t;
    for (int i = t; i < Dd; i += 64) s_sh[i] = g_s[h * Dd + i];
    __syncthreads();
    float acc = 0.f;
#pragma unroll 8
    for (int e = 0; e < Dd; e++) acc += s_sh[e] * w_v[e * Dd + d];
    g_O[d] = g_q[d] + acc + b_v[d];
}

// ---------------- K9: O2 = O + relu(O@w_o + b_o) ----------------
__global__ void k_o(const float* __restrict__ w_o, const float* __restrict__ b_o) {
    __shared__ float O_sh[Dd];
    int t = threadIdx.x;               // 64
    int d = blockIdx.x * 64 + t;
    for (int i = t; i < Dd; i += 64) O_sh[i] = g_O[i];
    __syncthreads();
    float acc = 0.f;
#pragma unroll 8
    for (int e = 0; e < Dd; e++) acc += O_sh[e] * w_o[e * Dd + d];
    g_O2[d] = g_O[d] + fmaxf(acc + b_o[d], 0.f);
}

// ---------------- K10: out = O2 @ w_fc + b_fc ----------------
__global__ void k_fc(const float* __restrict__ w_fc, const float* __restrict__ b_fc,
                     float* __restrict__ out) {
    __shared__ float r0[128], r1[128];
    int t = threadIdx.x;               // 128
    float a0 = 0.f, a1 = 0.f;
    for (int e = t; e < Dd; e += 128) {
        float o = g_O2[e];
        a0 += o * w_fc[e * 2 + 0];
        a1 += o * w_fc[e * 2 + 1];
    }
    r0[t] = a0; r1[t] = a1; __syncthreads();
    for (int o = 64; o; o >>= 1) {
        if (t < o) { r0[t] += r0[t + o]; r1[t] += r1[t + o]; }
        __syncthreads();
    }
    if (t == 0) { out[0] = r0[0] + b_fc[0]; out[1] = r1[0] + b_fc[1]; }
}

// ---------------- launch ----------------
extern "C" void kernel_launch(void* const* d_in, const int* in_sizes, int n_in,
                              void* d_out, int out_size) {
    const float* inputs = (const float*)d_in[0];
    const float* w_enc  = (const float*)d_in[1];
    const float* b_enc  = (const float*)d_in[2];
    const float* cls    = (const float*)d_in[3];
    const float* conv_w = (const float*)d_in[4];
    const float* conv_b = (const float*)d_in[5];
    const float* w_q    = (const float*)d_in[6];
    const float* b_q    = (const float*)d_in[7];
    const float* w_k    = (const float*)d_in[8];
    const float* b_k    = (const float*)d_in[9];
    const float* w_v    = (const float*)d_in[10];
    const float* b_v    = (const float*)d_in[11];
    const float* w_o    = (const float*)d_in[12];
    const float* b_o    = (const float*)d_in[13];
    const float* w_fc   = (const float*)d_in[14];
    const float* b_fc   = (const float*)d_in[15];

    float* out    = (float*)d_out;
    float* ishift = out + 2;                       // i_shift: [1,60000,512]
    float* A1     = out + 2 + (size_t)Nn * Dd;     // A1: [1,60000]

    k_init<<<1, 1>>>();
    k_enc<<<Nn / 8, 256>>>(inputs, w_enc, b_enc, A1);
    k_decode<<<1, 1>>>();
    k_q<<<8, 64>>>(inputs, w_q, b_q);
    k_u<<<8, 512>>>(w_k, b_k);
    k_conv<<<dim3(8, HH), Dd>>>(inputs, conv_w, conv_b, ishift);
    k_scores<<<512, 256>>>(cls);
    k_softmax<<<8, 256>>>();
    k_wsum<<<NBLK7, 128>>>(cls);
    k_wred<<<16, 256>>>();
    k_av<<<8, 64>>>(w_v, b_v);
    k_o<<<8, 64>>>(w_o, b_o);
    k_fc<<<1, 128>>>(w_fc, b_fc, out);
}

// round 2
// speedup vs baseline: 1.8941x; 1.8941x over previous
#include <cuda_runtime.h>
#include <math.h>

#define Nn 60000
#define Dd 512
#define HH 245
#define NPOS 60025
#define NSEQ 60026
#define SST 60032
#define RT 5
#define NBLK7 632
#define CHUNK7 95
#define SMAXB 32
#define INV_SQRT_D 0.04419417382415922f

// ---------------- scratch (device globals: allocation-free) ----------------
__device__ unsigned long long g_key;
__device__ int   g_idx;
__device__ float g_q[Dd];
__device__ float g_u[8 * Dd];
__device__ float g_c[8];
__device__ float g_xx[NPOS * Dd];          // ~123 MB conv output (xseq rows 1..)
__device__ float g_scores[8 * SST];
__device__ float g_mp[8 * SMAXB];
__device__ float g_sp[8 * SMAXB];
__device__ float g_m[8];
__device__ float g_rinv[8];
__device__ float g_spart[NBLK7 * 4096];
__device__ float g_s[4096];                // s[h][e] = sum_p attn[h,p]*xseq[p,e]
__device__ float g_gp[8 * Dd];             // gemv partials
__device__ float g_O[Dd];
__device__ float g_O2[Dd];

// ---------------- K0: per-launch init ----------------
__global__ void k_init() { g_key = 0ull; }

// ---------------- K1: a1 = sigmoid(inputs@w_enc+b), A1 out, argmax ----------------
__global__ void k_enc(const float* __restrict__ inputs,
                      const float* __restrict__ w_enc,
                      const float* __restrict__ b_enc,
                      float* __restrict__ a1_out) {
    __shared__ float w_sh[Dd];
    __shared__ unsigned long long keys[8];
    int t = threadIdx.x;               // 256 threads, 8 warps
    w_sh[t] = w_enc[t];
    w_sh[t + 256] = w_enc[t + 256];
    __syncthreads();
    int warp = t >> 5, lane = t & 31;
    int row = blockIdx.x * 8 + warp;
    float acc = 0.f;
    const float4* rp = (const float4*)(inputs + (size_t)row * Dd);
#pragma unroll
    for (int k = 0; k < 4; k++) {
        float4 v = rp[lane + 32 * k];
        const float* ws = &w_sh[(lane + 32 * k) * 4];
        acc += v.x * ws[0] + v.y * ws[1] + v.z * ws[2] + v.w * ws[3];
    }
#pragma unroll
    for (int o = 16; o; o >>= 1) acc += __shfl_xor_sync(0xFFFFFFFFu, acc, o);
    if (lane == 0) {
        float val = acc + b_enc[0];
        a1_out[row] = 1.0f / (1.0f + expf(-val));
        unsigned u = __float_as_uint(val);
        u = (u & 0x80000000u) ? ~u : (u | 0x80000000u);
        keys[warp] = ((unsigned long long)u << 32) | (unsigned long long)(0xFFFFFFFFu - (unsigned)row);
    }
    __syncthreads();
    if (t == 0) {
        unsigned long long k = keys[0];
#pragma unroll
        for (int i = 1; i < 8; i++) k = (keys[i] > k) ? keys[i] : k;
        atomicMax(&g_key, k);
    }
}

__global__ void k_decode() {
    g_idx = (int)(0xFFFFFFFFu - (unsigned)(g_key & 0xFFFFFFFFull));
}

// ---------------- K2: q = inputs[idx] @ w_q + b_q (split-e partials) ----------------
__global__ void k_q_part(const float* __restrict__ inputs,
                         const float* __restrict__ w_q) {
    __shared__ float xs[64];
    int t = threadIdx.x;               // 128
    int d = blockIdx.x * 128 + t;
    int e0 = blockIdx.y * 64;
    const float* x = inputs + (size_t)g_idx * Dd;
    if (t < 64) xs[t] = x[e0 + t];
    __syncthreads();
    float acc = 0.f;
#pragma unroll 8
    for (int j = 0; j < 64; j++) acc += xs[j] * w_q[(size_t)(e0 + j) * Dd + d];
    g_gp[blockIdx.y * Dd + d] = acc;
}

__global__ void k_q_red(const float* __restrict__ b_q) {
    int d = threadIdx.x;               // 512
    float acc = b_q[d];
#pragma unroll
    for (int i = 0; i < 8; i++) acc += g_gp[i * Dd + d];
    g_q[d] = acc;
}

// ---------------- K3: u[h][e] = sum_j w_k[e, h*64+j]*q[h*64+j]; c[h] ----------------
__global__ void k_u(const float* __restrict__ w_k,
                    const float* __restrict__ b_k) {
    __shared__ float qs[Dd];
    int t = threadIdx.x;               // 1024, 32 warps
    if (t < Dd) qs[t] = g_q[t];
    __syncthreads();
    int warp = t >> 5, lane = t & 31;
    int e = blockIdx.x * 32 + warp;    // 16 blocks -> 512 rows
    const float4* wr = (const float4*)(w_k + (size_t)e * Dd + lane * 16);
    const float4* qp = (const float4*)(qs + lane * 16);
    float acc = 0.f;
#pragma unroll
    for (int k = 0; k < 4; k++) {
        float4 w = wr[k];
        float4 q = qp[k];
        acc += w.x * q.x + w.y * q.y + w.z * q.z + w.w * q.w;
    }
    acc += __shfl_xor_sync(0xFFFFFFFFu, acc, 1);
    acc += __shfl_xor_sync(0xFFFFFFFFu, acc, 2);
    if ((lane & 3) == 0) g_u[(lane >> 2) * Dd + e] = acc;
    if (blockIdx.x == 0 && t < 8) {
        float cc = 0.f;
        for (int j = 0; j < 64; j++) cc += b_k[t * 64 + j] * qs[t * 64 + j];
        g_c[t] = cc;
    }
}

// ---------------- K5: fused xs=relu(x-Q) + depthwise 3x3 conv + residual ----------------
__device__ __forceinline__ float xp_val(const float* __restrict__ inp,
                                        int rr, int cc, int d, float Qd) {
    if (rr < 0 || rr >= HH || cc < 0 || cc >= HH) return 0.f;
    int pos = rr * HH + cc;
    int src = (pos >= Nn) ? pos - Nn : pos;
    return fmaxf(__ldg(inp + (size_t)src * Dd + d) - Qd, 0.f);
}

__global__ void k_conv(const float* __restrict__ inputs,
                       const float* __restrict__ conv_w,
                       const float* __restrict__ conv_b,
                       float* __restrict__ ishift) {
    int d = threadIdx.x;               // 512 (one per channel)
    int rt = blockIdx.y * RT;          // row tile: RT output rows
    int c0 = blockIdx.x * 32;          // 8 col-segments of 32
    if (c0 >= HH) return;
    int cend = min(HH, c0 + 32);
    float w[9];
#pragma unroll
    for (int k = 0; k < 9; k++) w[k] = conv_w[d * 9 + k];
    float cb = conv_b[d];
    int idx = g_idx;
    float Qd = inputs[(size_t)idx * Dd + d];

    float vA[RT + 2], vB[RT + 2], vC[RT + 2];
#pragma unroll
    for (int i = 0; i < RT + 2; i++) {
        vA[i] = xp_val(inputs, rt - 1 + i, c0 - 1, d, Qd);
        vB[i] = xp_val(inputs, rt - 1 + i, c0,     d, Qd);
    }
    for (int c = c0; c < cend; c++) {
#pragma unroll
        for (int i = 0; i < RT + 2; i++)
            vC[i] = xp_val(inputs, rt - 1 + i, c + 1, d, Qd);
#pragma unroll
        for (int k = 0; k < RT; k++) {
            int r = rt + k;
            float xx = vB[k + 1] + cb
                     + w[0] * vA[k]     + w[1] * vB[k]     + w[2] * vC[k]
                     + w[3] * vA[k + 1] + w[4] * vB[k + 1] + w[5] * vC[k + 1]
                     + w[6] * vA[k + 2] + w[7] * vB[k + 2] + w[8] * vC[k + 2];
            int pos = r * HH + c;
            if (pos < Nn) ishift[(size_t)pos * Dd + d] = vB[k + 1];
            g_xx[(size_t)pos * Dd + d] = xx;
        }
#pragma unroll
        for (int i = 0; i < RT + 2; i++) { vA[i] = vB[i]; vB[i] = vC[i]; }
    }
}

// ---------------- K6a: scores[h,p] = (xseq[p].u_h + c_h)/sqrt(D) ----------------
__global__ void k_scores(const float* __restrict__ cls) {
    __shared__ float4 u_sh[8 * 128];   // u as float4 per head
    int t = threadIdx.x;               // 256, 8 warps
    float* uf = (float*)u_sh;
    for (int i = t; i < 4096; i += 256) uf[i] = g_u[i];
    __syncthreads();
    int warp = t >> 5, lane = t & 31;
    int stride = gridDim.x * 8;
    for (int p = blockIdx.x * 8 + warp; p < NSEQ; p += stride) {
        const float4* rp = (p == 0) ? (const float4*)cls
                                    : (const float4*)(g_xx + (size_t)(p - 1) * Dd);
        float4 rv[4];
#pragma unroll
        for (int k = 0; k < 4; k++) rv[k] = rp[k * 32 + lane];
        float sc[8];
#pragma unroll
        for (int h = 0; h < 8; h++) {
            float acc = 0.f;
#pragma unroll
            for (int k = 0; k < 4; k++) {
                float4 u = u_sh[h * 128 + k * 32 + lane];
                acc += rv[k].x * u.x + rv[k].y * u.y + rv[k].z * u.z + rv[k].w * u.w;
            }
            sc[h] = acc;
        }
#pragma unroll
        for (int h = 0; h < 8; h++)
#pragma unroll
            for (int o = 16; o; o >>= 1) sc[h] += __shfl_xor_sync(0xFFFFFFFFu, sc[h], o);
        if (lane < 8) g_scores[lane * SST + p] = (sc[lane] + g_c[lane]) * INV_SQRT_D;
    }
}

// ---------------- K6b: parallel softmax stats ----------------
__global__ void k_smax1() {
    int h = blockIdx.y, b = blockIdx.x, t = threadIdx.x;   // (32,8) x 256
    __shared__ float red[256];
    const int chunk = 1876;            // 32*1876 = 60032 >= NSEQ
    int p0 = b * chunk;
    int p1 = min(NSEQ, p0 + chunk);
    const float* s = g_scores + h * SST;
    float m = -1e30f;
    for (int p = p0 + t; p < p1; p += 256) m = fmaxf(m, s[p]);
    red[t] = m; __syncthreads();
    for (int o = 128; o; o >>= 1) { if (t < o) red[t] = fmaxf(red[t], red[t + o]); __syncthreads(); }
    m = red[0]; __syncthreads();
    float sum = 0.f;
    for (int p = p0 + t; p < p1; p += 256) sum += expf(s[p] - m);
    red[t] = sum; __syncthreads();
    for (int o = 128; o; o >>= 1) { if (t < o) red[t] += red[t + o]; __syncthreads(); }
    if (t == 0) { g_mp[h * SMAXB + b] = m; g_sp[h * SMAXB + b] = red[0]; }
}

__global__ void k_smax2() {
    int h = blockIdx.x, lane = threadIdx.x;  // 8 x 32
    float m_b = g_mp[h * SMAXB + lane];
    float s_b = g_sp[h * SMAXB + lane];
    float m = m_b;
#pragma unroll
    for (int o = 16; o; o >>= 1) m = fmaxf(m, __shfl_xor_sync(0xFFFFFFFFu, m, o));
    float s = s_b * expf(m_b - m);
#pragma unroll
    for (int o = 16; o; o >>= 1) s += __shfl_xor_sync(0xFFFFFFFFu, s, o);
    if (lane == 0) { g_m[h] = m; g_rinv[h] = 1.0f / s; }
}

// ---------------- K7: s[h][e] = sum_p attn[h,p]*xseq[p,e] (block partials) ----------------
__global__ void k_wsum(const float* __restrict__ cls) {
    int b = blockIdx.x, t = threadIdx.x;   // NBLK7 x 128 (float4 channels)
    int p0 = b * CHUNK7;
    int p1 = min(NSEQ, p0 + CHUNK7);
    __shared__ float wsh[CHUNK7 * 8];
    __shared__ float mh[8], rh[8];
    if (t < 8) { mh[t] = g_m[t]; rh[t] = g_rinv[t]; }
    __syncthreads();
    for (int i = t; i < (p1 - p0) * 8; i += 128) {
        int pp = i >> 3, h = i & 7;
        wsh[i] = expf(g_scores[h * SST + p0 + pp] - mh[h]) * rh[h];
    }
    __syncthreads();
    float acc[8][4];
#pragma unroll
    for (int h = 0; h < 8; h++) { acc[h][0] = acc[h][1] = acc[h][2] = acc[h][3] = 0.f; }
#pragma unroll 2
    for (int p = p0; p < p1; p++) {
        const float4* rp = (p == 0) ? (const float4*)cls
                                    : (const float4*)(g_xx + (size_t)(p - 1) * Dd);
        float4 v = rp[t];
        const float* wp = &wsh[(p - p0) * 8];
#pragma unroll
        for (int h = 0; h < 8; h++) {
            float w = wp[h];
            acc[h][0] += w * v.x; acc[h][1] += w * v.y;
            acc[h][2] += w * v.z; acc[h][3] += w * v.w;
        }
    }
    float* outp = g_spart + (size_t)b * 4096;
#pragma unroll
    for (int h = 0; h < 8; h++)
        ((float4*)(outp + h * Dd))[t] = make_float4(acc[h][0], acc[h][1], acc[h][2], acc[h][3]);
}

__global__ void k_wred() {
    int i = blockIdx.x * 256 + threadIdx.x;  // 16 x 256 = 4096
    float acc = 0.f;
    for (int b = 0; b < NBLK7; b++) acc += g_spart[(size_t)b * 4096 + i];
    g_s[i] = acc;
}

// ---------------- K8: O[d] = q[d] + s[h(d)].w_v[:,d] + b_v[d] ----------------
__global__ void k_av_part(const float* __restrict__ w_v) {
    __shared__ float xs[64];
    int h = blockIdx.x, t = threadIdx.x;   // (8,8) x 64
    int d = h * 64 + t;
    int e0 = blockIdx.y * 64;
    xs[t] = g_s[h * Dd + e0 + t];
    __syncthreads();
    float acc = 0.f;
#pragma unroll 8
    for (int j = 0; j < 64; j++) acc += xs[j] * w_v[(size_t)(e0 + j) * Dd + d];
    g_gp[blockIdx.y * Dd + d] = acc;
}

__global__ void k_av_red(const float* __restrict__ b_v) {
    int d = threadIdx.x;               // 512
    float acc = b_v[d];
#pragma unroll
    for (int i = 0; i < 8; i++) acc += g_gp[i * Dd + d];
    g_O[d] = g_q[d] + acc;
}

// ---------------- K9: O2 = O + relu(O@w_o + b_o) ----------------
__global__ void k_o_part(const float* __restrict__ w_o) {
    __shared__ float xs[64];
    int t = threadIdx.x;               // (4,8) x 128
    int d = blockIdx.x * 128 + t;
    int e0 = blockIdx.y * 64;
    if (t < 64) xs[t] = g_O[e0 + t];
    __syncthreads();
    float acc = 0.f;
#pragma unroll 8
    for (int j = 0; j < 64; j++) acc += xs[j] * w_o[(size_t)(e0 + j) * Dd + d];
    g_gp[blockIdx.y * Dd + d] = acc;
}

__global__ void k_o_red(const float* __restrict__ b_o) {
    int d = threadIdx.x;               // 512
    float acc = b_o[d];
#pragma unroll
    for (int i = 0; i < 8; i++) acc += g_gp[i * Dd + d];
    g_O2[d] = g_O[d] + fmaxf(acc, 0.f);
}

// ---------------- K10: out = O2 @ w_fc + b_fc ----------------
__global__ void k_fc(const float* __restrict__ w_fc, const float* __restrict__ b_fc,
                     float* __restrict__ out) {
    __shared__ float r0[128], r1[128];
    int t = threadIdx.x;               // 128
    float a0 = 0.f, a1 = 0.f;
    for (int e = t; e < Dd; e += 128) {
        float o = g_O2[e];
        a0 += o * w_fc[e * 2 + 0];
        a1 += o * w_fc[e * 2 + 1];
    }
    r0[t] = a0; r1[t] = a1; __syncthreads();
    for (int o = 64; o; o >>= 1) {
        if (t < o) { r0[t] += r0[t + o]; r1[t] += r1[t + o]; }
        __syncthreads();
    }
    if (t == 0) { out[0] = r0[0] + b_fc[0]; out[1] = r1[0] + b_fc[1]; }
}

// ---------------- launch ----------------
extern "C" void kernel_launch(void* const* d_in, const int* in_sizes, int n_in,
                              void* d_out, int out_size) {
    const float* inputs = (const float*)d_in[0];
    const float* w_enc  = (const float*)d_in[1];
    const float* b_enc  = (const float*)d_in[2];
    const float* cls    = (const float*)d_in[3];
    const float* conv_w = (const float*)d_in[4];
    const float* conv_b = (const float*)d_in[5];
    const float* w_q    = (const float*)d_in[6];
    const float* b_q    = (const float*)d_in[7];
    const float* w_k    = (const float*)d_in[8];
    const float* b_k    = (const float*)d_in[9];
    const float* w_v    = (const float*)d_in[10];
    const float* b_v    = (const float*)d_in[11];
    const float* w_o    = (const float*)d_in[12];
    const float* b_o    = (const float*)d_in[13];
    const float* w_fc   = (const float*)d_in[14];
    const float* b_fc   = (const float*)d_in[15];

    float* out    = (float*)d_out;
    float* ishift = out + 2;                       // i_shift: [1,60000,512]
    float* A1     = out + 2 + (size_t)Nn * Dd;     // A1: [1,60000]

    k_init<<<1, 1>>>();
    k_enc<<<Nn / 8, 256>>>(inputs, w_enc, b_enc, A1);
    k_decode<<<1, 1>>>();
    k_q_part<<<dim3(4, 8), 128>>>(inputs, w_q);
    k_q_red<<<1, 512>>>(b_q);
    k_u<<<16, 1024>>>(w_k, b_k);
    k_conv<<<dim3(8, HH / RT), Dd>>>(inputs, conv_w, conv_b, ishift);
    k_scores<<<512, 256>>>(cls);
    k_smax1<<<dim3(SMAXB, 8), 256>>>();
    k_smax2<<<8, 32>>>();
    k_wsum<<<NBLK7, 128>>>(cls);
    k_wred<<<16, 256>>>();
    k_av_part<<<dim3(8, 8), 64>>>(w_v);
    k_av_red<<<1, 512>>>(b_v);
    k_o_part<<<dim3(4, 8), 128>>>(w_o);
    k_o_red<<<1, 512>>>(b_o);
    k_fc<<<1, 128>>>(w_fc, b_fc, out);
}